// round 1
// baseline (speedup 1.0000x reference)
#include <cuda_runtime.h>

#define NMAX   16384
#define TPB    256
#define RPT    4
#define TILE_Y 512

__device__ float g_minA[NMAX];  // rows = pred vs gt
__device__ float g_minB[NMAX];  // rows = gt vs pred

__device__ __forceinline__ float inf_f() { return __int_as_float(0x7f800000); }

__global__ void init_kernel(int np, int ng) {
    int i = blockIdx.x * blockDim.x + threadIdx.x;
    if (i < np) g_minA[i] = inf_f();
    if (i < ng) g_minB[i] = inf_f();
}

// Mixed-sign atomic float min: positives via int-min, negatives via uint-max.
// Converges to the true min regardless of interleaving (init = +INF).
__device__ __forceinline__ void atomicMinF(float* addr, float val) {
    if (val >= 0.0f) atomicMin((int*)addr, __float_as_int(val));
    else             atomicMax((unsigned int*)addr, __float_as_uint(val));
}

// For each row point x in X, compute min over column points y in Y of
//   t = 0.5*||y||^2 - x.y      (so that min d2 = ||x||^2 + 2*min t)
// blockIdx.z selects direction. blockIdx.y selects a y-chunk (partial mins
// merged with atomicMinF).
__global__ void pass_kernel(const float* __restrict__ P, const float* __restrict__ G,
                            int NP, int NG, int ychunks) {
    const float* X; const float* Y; int NX, NY; float* omin;
    if (blockIdx.z == 0) { X = P; Y = G; NX = NP; NY = NG; omin = g_minA; }
    else                 { X = G; Y = P; NX = NG; NY = NP; omin = g_minB; }

    __shared__ float4 sy[TILE_Y];
    const int tid  = threadIdx.x;
    const int row0 = blockIdx.x * (TPB * RPT) + tid;

    float x0[RPT], x1[RPT], x2[RPT], tmin[RPT];
#pragma unroll
    for (int k = 0; k < RPT; k++) {
        int r = row0 + k * TPB;
        if (r < NX) { x0[k] = X[3*r]; x1[k] = X[3*r+1]; x2[k] = X[3*r+2]; }
        else        { x0[k] = 0.f; x1[k] = 0.f; x2[k] = 0.f; }
        tmin[k] = inf_f();
    }

    const int chunk = (NY + ychunks - 1) / ychunks;
    const int yb = blockIdx.y * chunk;
    const int ye = min(yb + chunk, NY);

    for (int t0 = yb; t0 < ye; t0 += TILE_Y) {
        const int tn = ye - t0;  // may be < TILE_Y on the ragged tail
        __syncthreads();
        for (int j = tid; j < TILE_Y; j += TPB) {
            float4 v;
            if (j < tn) {
                int g = t0 + j;
                float a = Y[3*g], b = Y[3*g+1], c = Y[3*g+2];
                v = make_float4(a, b, c, 0.5f * (a*a + b*b + c*c));
            } else {
                v = make_float4(0.f, 0.f, 0.f, inf_f());  // sentinel: t = +INF
            }
            sy[j] = v;
        }
        __syncthreads();

#pragma unroll 4
        for (int j = 0; j < TILE_Y; j++) {
            float4 y = sy[j];
#pragma unroll
            for (int k = 0; k < RPT; k++) {
                float t = y.w;                   // 0.5*||y||^2
                t = fmaf(-x0[k], y.x, t);
                t = fmaf(-x1[k], y.y, t);
                t = fmaf(-x2[k], y.z, t);
                tmin[k] = fminf(tmin[k], t);
            }
        }
    }

#pragma unroll
    for (int k = 0; k < RPT; k++) {
        int r = row0 + k * TPB;
        if (r < NX) atomicMinF(&omin[r], tmin[k]);
    }
}

__global__ void finalize_kernel(const float* __restrict__ P, const float* __restrict__ G,
                                int NP, int NG, float* __restrict__ out) {
    __shared__ float ssum[32];
    const int tid = threadIdx.x;
    const float wP = 1.0f / (float)NP;
    const float wG = 1.0f / (float)NG;
    float acc = 0.f;

    for (int i = tid; i < NP; i += blockDim.x) {
        float a = P[3*i], b = P[3*i+1], c = P[3*i+2];
        float d2 = fmaf(a, a, fmaf(b, b, c*c)) + 2.0f * g_minA[i];
        acc += sqrtf(fmaxf(d2, 0.f)) * wP;
    }
    for (int i = tid; i < NG; i += blockDim.x) {
        float a = G[3*i], b = G[3*i+1], c = G[3*i+2];
        float d2 = fmaf(a, a, fmaf(b, b, c*c)) + 2.0f * g_minB[i];
        acc += sqrtf(fmaxf(d2, 0.f)) * wG;
    }

#pragma unroll
    for (int o = 16; o > 0; o >>= 1) acc += __shfl_down_sync(0xffffffffu, acc, o);
    if ((tid & 31) == 0) ssum[tid >> 5] = acc;
    __syncthreads();
    if (tid < 32) {
        int nwarps = (blockDim.x + 31) >> 5;
        float v = (tid < nwarps) ? ssum[tid] : 0.f;
#pragma unroll
        for (int o = 16; o > 0; o >>= 1) v += __shfl_down_sync(0xffffffffu, v, o);
        if (tid == 0) out[0] = v;
    }
}

extern "C" void kernel_launch(void* const* d_in, const int* in_sizes, int n_in,
                              void* d_out, int out_size) {
    const float* P = (const float*)d_in[0];
    const float* G = (const float*)d_in[1];
    const int NP = in_sizes[0] / 3;
    const int NG = in_sizes[1] / 3;
    float* out = (float*)d_out;

    const int nmax = NP > NG ? NP : NG;
    init_kernel<<<(nmax + 255) / 256, 256>>>(NP, NG);

    const int ychunks = 32;  // 16 x 32 x 2 = 1024 blocks ~ 6.9 per SM
    dim3 grid((nmax + TPB * RPT - 1) / (TPB * RPT), ychunks, 2);
    pass_kernel<<<grid, TPB>>>(P, G, NP, NG, ychunks);

    finalize_kernel<<<1, 512>>>(P, G, NP, NG, out);
}

// round 2
// speedup vs baseline: 1.0210x; 1.0210x over previous
#include <cuda_runtime.h>

#define NMAX      16384
#define TPB       256
#define RPT       8                    // rows per thread (4 packed pairs)
#define ROWS_BLK  (TPB * RPT)          // 2048 rows per block
#define TILE_CAP  128                  // max columns staged in smem per tile
#define YCHUNKS   148                  // grid.y -> 8*148*2 = 2368 blocks = 16/SM

__device__ float g_minA[NMAX];  // min over gt  for each pred point (stores t = 0.5||y||^2 - x.y)
__device__ float g_minB[NMAX];  // min over pred for each gt point

typedef unsigned long long ull;

__device__ __forceinline__ float inf_f() { return __int_as_float(0x7f800000); }

__device__ __forceinline__ ull pack2(float lo, float hi) {
    ull r; asm("mov.b64 %0, {%1, %2};" : "=l"(r) : "f"(lo), "f"(hi)); return r;
}
__device__ __forceinline__ void unpack2(ull v, float& lo, float& hi) {
    asm("mov.b64 {%0, %1}, %2;" : "=f"(lo), "=f"(hi) : "l"(v));
}
__device__ __forceinline__ ull ffma2(ull a, ull b, ull c) {
    ull d; asm("fma.rn.f32x2 %0, %1, %2, %3;" : "=l"(d) : "l"(a), "l"(b), "l"(c)); return d;
}

__global__ void init_kernel(int np, int ng) {
    int i = blockIdx.x * blockDim.x + threadIdx.x;
    if (i < np) g_minA[i] = inf_f();
    if (i < ng) g_minB[i] = inf_f();
}

// Mixed-sign atomic float min: positives via signed int-min, negatives via uint-max.
__device__ __forceinline__ void atomicMinF(float* addr, float val) {
    if (val >= 0.0f) atomicMin((int*)addr, __float_as_int(val));
    else             atomicMax((unsigned int*)addr, __float_as_uint(val));
}

struct __align__(16) YCol {      // pre-duplicated packed operands: 32 B per column
    ull yxx;   // (y.x, y.x)
    ull yyy;   // (y.y, y.y)
    ull yzz;   // (y.z, y.z)
    ull ccc;   // (0.5||y||^2, 0.5||y||^2)
};

// For each row point x in X: min over column points y of t = 0.5||y||^2 - x.y
// (min d2 = ||x||^2 + 2*min t). blockIdx.z = direction, blockIdx.y = y-chunk.
__global__ void __launch_bounds__(TPB, 4)
pass_kernel(const float* __restrict__ P, const float* __restrict__ G,
            int NP, int NG) {
    const float* X; const float* Y; int NX, NY; float* omin;
    if (blockIdx.z == 0) { X = P; Y = G; NX = NP; NY = NG; omin = g_minA; }
    else                 { X = G; Y = P; NX = NG; NY = NP; omin = g_minB; }

    __shared__ YCol sy[TILE_CAP];
    const int tid  = threadIdx.x;
    const int row0 = blockIdx.x * ROWS_BLK + tid;

    // Pack row coords negated: packed pair p covers rows (row0+2p*TPB, row0+(2p+1)*TPB)
    ull nx0[RPT/2], nx1[RPT/2], nx2[RPT/2];
    float tmin[RPT];
#pragma unroll
    for (int p = 0; p < RPT/2; p++) {
        float a0 = 0.f, b0 = 0.f, c0 = 0.f, a1 = 0.f, b1 = 0.f, c1 = 0.f;
        int r0 = row0 + (2*p)     * TPB;
        int r1 = row0 + (2*p + 1) * TPB;
        if (r0 < NX) { a0 = X[3*r0]; b0 = X[3*r0+1]; c0 = X[3*r0+2]; }
        if (r1 < NX) { a1 = X[3*r1]; b1 = X[3*r1+1]; c1 = X[3*r1+2]; }
        nx0[p] = pack2(-a0, -a1);
        nx1[p] = pack2(-b0, -b1);
        nx2[p] = pack2(-c0, -c1);
        tmin[2*p] = inf_f(); tmin[2*p+1] = inf_f();
    }

    const int gy    = gridDim.y;
    const int chunk = (NY + gy - 1) / gy;
    const int yb    = blockIdx.y * chunk;
    const int ye    = min(yb + chunk, NY);

    for (int t0 = yb; t0 < ye; t0 += TILE_CAP) {
        const int tn = min(TILE_CAP, ye - t0);
        __syncthreads();
        for (int j = tid; j < tn; j += TPB) {
            int g = t0 + j;
            float a = Y[3*g], b = Y[3*g+1], c = Y[3*g+2];
            float cc = 0.5f * (a*a + b*b + c*c);
            sy[j].yxx = pack2(a, a);
            sy[j].yyy = pack2(b, b);
            sy[j].yzz = pack2(c, c);
            sy[j].ccc = pack2(cc, cc);
        }
        __syncthreads();

#pragma unroll 2
        for (int j = 0; j < tn; j++) {
            // two LDS.128 fetch the 4 packed broadcast operands
            ulonglong2 ab = *(const ulonglong2*)(&sy[j].yxx);
            ulonglong2 cd = *(const ulonglong2*)(&sy[j].yzz);
#pragma unroll
            for (int p = 0; p < RPT/2; p++) {
                ull t = ffma2(nx0[p], ab.x, cd.y);   // 0.5||y||^2 - x0*yx
                t = ffma2(nx1[p], ab.y, t);
                t = ffma2(nx2[p], cd.x, t);
                float lo, hi; unpack2(t, lo, hi);    // register-pair aliasing, no instr
                tmin[2*p]   = fminf(tmin[2*p],   lo);
                tmin[2*p+1] = fminf(tmin[2*p+1], hi);
            }
        }
    }

#pragma unroll
    for (int k = 0; k < RPT; k++) {
        int r = row0 + ((k & 1) ? (k/2)*2 + 1 : (k/2)*2) * TPB;  // same mapping as pack
        r = row0 + k * TPB;  // pair p covers k=2p,2p+1 -> identical linear mapping
        if (r < NX) atomicMinF(&omin[r], tmin[k]);
    }
}

__global__ void finalize_kernel(const float* __restrict__ P, const float* __restrict__ G,
                                int NP, int NG, float* __restrict__ out) {
    __shared__ float ssum[32];
    const int tid = threadIdx.x;
    const float wP = 1.0f / (float)NP;
    const float wG = 1.0f / (float)NG;
    float acc = 0.f;

    for (int i = tid; i < NP; i += blockDim.x) {
        float a = P[3*i], b = P[3*i+1], c = P[3*i+2];
        float d2 = fmaf(a, a, fmaf(b, b, c*c)) + 2.0f * g_minA[i];
        acc += sqrtf(fmaxf(d2, 0.f)) * wP;
    }
    for (int i = tid; i < NG; i += blockDim.x) {
        float a = G[3*i], b = G[3*i+1], c = G[3*i+2];
        float d2 = fmaf(a, a, fmaf(b, b, c*c)) + 2.0f * g_minB[i];
        acc += sqrtf(fmaxf(d2, 0.f)) * wG;
    }

#pragma unroll
    for (int o = 16; o > 0; o >>= 1) acc += __shfl_down_sync(0xffffffffu, acc, o);
    if ((tid & 31) == 0) ssum[tid >> 5] = acc;
    __syncthreads();
    if (tid < 32) {
        int nwarps = (blockDim.x + 31) >> 5;
        float v = (tid < nwarps) ? ssum[tid] : 0.f;
#pragma unroll
        for (int o = 16; o > 0; o >>= 1) v += __shfl_down_sync(0xffffffffu, v, o);
        if (tid == 0) out[0] = v;
    }
}

extern "C" void kernel_launch(void* const* d_in, const int* in_sizes, int n_in,
                              void* d_out, int out_size) {
    const float* P = (const float*)d_in[0];
    const float* G = (const float*)d_in[1];
    const int NP = in_sizes[0] / 3;
    const int NG = in_sizes[1] / 3;
    float* out = (float*)d_out;

    const int nmax = NP > NG ? NP : NG;
    init_kernel<<<(nmax + 255) / 256, 256>>>(NP, NG);

    dim3 grid((nmax + ROWS_BLK - 1) / ROWS_BLK, YCHUNKS, 2);
    pass_kernel<<<grid, TPB>>>(P, G, NP, NG);

    finalize_kernel<<<1, 512>>>(P, G, NP, NG, out);
}